// round 14
// baseline (speedup 1.0000x reference)
#include <cuda_runtime.h>
#include <cuda_bf16.h>
#include <cuda_fp16.h>
#include <cstdint>

#define NN 50000
#define NE 800000
#define DIM 128
#define NG 64
#define SEG 64            // fixed CSR slots per node (max deg ~45 for Poisson(16))

// ---------------- static device scratch -------------------------------------
static __device__ float    g_hA [NN * DIM];       // fp32 layer outputs (ping)
static __device__ float    g_hB [NN * DIM];       // fp32 layer outputs (pong)
static __device__ uint16_t g_aggh[NN * DIM];      // bf16 hi of mean-agg
static __device__ uint16_t g_aggl[NN * DIM];      // bf16 lo
static __device__ uint16_t g_xh[NN * DIM];        // bf16 hi of x
static __device__ uint16_t g_xl[NN * DIM];
static __device__ uint16_t g_hh0[NN * DIM];       // bf16 hi of h0
static __device__ uint16_t g_hl0[NN * DIM];
static __device__ uint16_t g_hh1[NN * DIM];       // bf16 hi of h1
static __device__ uint16_t g_hl1[NN * DIM];
static __device__ uint16_t g_xf16[NN * DIM];      // fp16 gather table for layer0
static __device__ uint16_t g_hf0 [NN * DIM];      // fp16 gather table for layer1
static __device__ uint16_t g_hf1 [NN * DIM];      // fp16 gather table for layer2
static __device__ uint16_t g_Wbh[6 * 16384];      // bf16 hi of Wl0,Wr0,Wl1,Wr1,Wl2,Wr2
static __device__ uint16_t g_Wbl[6 * 16384];
static __device__ int   g_deg[NN];                // doubles as fill cursor
static __device__ int   g_csr[NN * SEG];
static __device__ int   g_gcnt[NG];

// ---------------- helpers ----------------------------------------------------
__device__ __forceinline__ uint32_t smem_u32(const void* p) {
    uint32_t a;
    asm("{ .reg .u64 t; cvta.to.shared.u64 t, %1; cvt.u32.u64 %0, t; }"
        : "=r"(a) : "l"(p));
    return a;
}

__device__ __forceinline__ void bf16_split(float v, uint16_t& h, uint16_t& l) {
    __nv_bfloat16 hb = __float2bfloat16(v);
    float hf = __bfloat162float(hb);
    __nv_bfloat16 lb = __float2bfloat16(v - hf);
    h = __bfloat16_as_ushort(hb);
    l = __bfloat16_as_ushort(lb);
}

#define LDSM_X4(r, addr) \
    asm volatile("ldmatrix.sync.aligned.m8n8.x4.shared.b16 {%0,%1,%2,%3}, [%4];" \
        : "=r"((r)[0]), "=r"((r)[1]), "=r"((r)[2]), "=r"((r)[3]) : "r"(addr))

#define MMA_BF16(d, a, b0v, b1v) \
    asm volatile("mma.sync.aligned.m16n8k16.row.col.f32.bf16.bf16.f32 " \
        "{%0,%1,%2,%3}, {%4,%5,%6,%7}, {%8,%9}, {%0,%1,%2,%3};" \
        : "+f"((d)[0]), "+f"((d)[1]), "+f"((d)[2]), "+f"((d)[3]) \
        : "r"((a)[0]), "r"((a)[1]), "r"((a)[2]), "r"((a)[3]), \
          "r"(b0v), "r"(b1v))

#define CP_A16(dst32, src) \
    asm volatile("cp.async.cg.shared.global [%0], [%1], 16;" \
        :: "r"(dst32), "l"(src) : "memory")
#define CP_COMMIT  asm volatile("cp.async.commit_group;" ::: "memory")
#define CP_WAIT0   asm volatile("cp.async.wait_group 0;" ::: "memory")

// ---------------- init --------------------------------------------------------
__global__ void k_zero(float* __restrict__ out) {
    int i = blockIdx.x * blockDim.x + threadIdx.x;
    if (i < NN) g_deg[i] = 0;
    if (i < NG) g_gcnt[i] = 0;
    if (i < NG * DIM) out[i] = 0.0f;      // pool accumulators (d_out poisoned)
}

// cvtX (bf16 split + fp16) + CSR build + graph count + all W conversions
__global__ void k_prep(const float* __restrict__ x, const int* __restrict__ ei,
                       const int* __restrict__ batch,
                       const float* __restrict__ w0, const float* __restrict__ w1,
                       const float* __restrict__ w2, const float* __restrict__ w3,
                       const float* __restrict__ w4, const float* __restrict__ w5)
{
    int i = blockIdx.x * blockDim.x + threadIdx.x;
    if (i < NN * DIM) {
        float v = x[i];
        uint16_t h, l;
        bf16_split(v, h, l);
        g_xh[i] = h; g_xl[i] = l;
        g_xf16[i] = __half_as_ushort(__float2half_rn(v));
    }
    if (i < NE) {
        int s = ei[i];
        int d = ei[NE + i];
        int pos = atomicAdd(&g_deg[d], 1);
        g_csr[d * SEG + pos] = s;
    }
    if (i < NN) atomicAdd(&g_gcnt[batch[i]], 1);
    if (i < 6 * 16384) {
        int sel = i >> 14;
        int off = i & 16383;
        const float* w = (sel == 0) ? w0 : (sel == 1) ? w1 : (sel == 2) ? w2
                       : (sel == 3) ? w3 : (sel == 4) ? w4 : w5;
        uint16_t h, l;
        bf16_split(w[off], h, l);
        g_Wbh[i] = h; g_Wbl[i] = l;
    }
}

// ---------------- mean aggregation (warp per node, 2-edge-per-LDG gather) ---
// lanes 0-15 carry edge e0 (8 fp16 per lane = full 128-feat row), 16-31 edge e1
__global__ void k_agg(int sel) {
    const uint16_t* hf = (sel == 0) ? g_xf16 : ((sel == 1) ? g_hf0 : g_hf1);
    int gw   = (blockIdx.x * blockDim.x + threadIdx.x) >> 5;
    int lane = threadIdx.x & 31;
    if (gw >= NN) return;
    int start = gw * SEG;
    int d     = g_deg[gw];
    const uint4* x4 = (const uint4*)hf;   // 8 fp16 per lane-slot, 16 slots/row
    int half16 = lane >> 4;               // 0: even edge, 1: odd edge
    int fl     = lane & 15;               // feature slot
    float a[8] = {0.f, 0.f, 0.f, 0.f, 0.f, 0.f, 0.f, 0.f};

#define ACC8(v) { \
        float2 p0 = __half22float2(*(__half2*)&(v).x); \
        float2 p1 = __half22float2(*(__half2*)&(v).y); \
        float2 p2 = __half22float2(*(__half2*)&(v).z); \
        float2 p3 = __half22float2(*(__half2*)&(v).w); \
        a[0] += p0.x; a[1] += p0.y; a[2] += p1.x; a[3] += p1.y; \
        a[4] += p2.x; a[5] += p2.y; a[6] += p3.x; a[7] += p3.y; }

    int j = 0;
    for (; j + 4 <= d; j += 4) {
        int4 e = *(const int4*)&g_csr[start + j];
        int e01 = half16 ? e.y : e.x;
        int e23 = half16 ? e.w : e.z;
        uint4 v0 = x4[e01 * 16 + fl];
        uint4 v1 = x4[e23 * 16 + fl];
        ACC8(v0)
        ACC8(v1)
    }
    if (j + 2 <= d) {
        int2 e = *(const int2*)&g_csr[start + j];
        int eid = half16 ? e.y : e.x;
        uint4 v = x4[eid * 16 + fl];
        ACC8(v)
        j += 2;
    }
    if (j < d && half16 == 0) {
        int eid = g_csr[start + j];
        uint4 v = x4[eid * 16 + fl];
        ACC8(v)
    }
#undef ACC8

    // combine even-edge (lanes 0-15) and odd-edge (lanes 16-31) partial sums
#pragma unroll
    for (int i = 0; i < 8; i++)
        a[i] += __shfl_xor_sync(0xffffffffu, a[i], 16);

    if (half16 == 0) {
        float inv = (d > 0) ? 1.0f / (float)d : 0.0f;
        uint16_t h[8], l[8];
#pragma unroll
        for (int i = 0; i < 8; i++) {
            a[i] *= inv;
            bf16_split(a[i], h[i], l[i]);
        }
        int idx = gw * 128 + fl * 8;
        *(uint4*)&g_aggh[idx] = make_uint4(
            (uint32_t)h[0] | ((uint32_t)h[1] << 16),
            (uint32_t)h[2] | ((uint32_t)h[3] << 16),
            (uint32_t)h[4] | ((uint32_t)h[5] << 16),
            (uint32_t)h[6] | ((uint32_t)h[7] << 16));
        *(uint4*)&g_aggl[idx] = make_uint4(
            (uint32_t)l[0] | ((uint32_t)l[1] << 16),
            (uint32_t)l[2] | ((uint32_t)l[3] << 16),
            (uint32_t)l[4] | ((uint32_t)l[5] << 16),
            (uint32_t)l[6] | ((uint32_t)l[7] << 16));
    }
}

// ---------------- bf16-split tensor GEMM (cp.async double-buffered) ---------
#define AST 40            // smem row stride in u16 (80B -> conflict-free ldmatrix)
#define TILE_E 5120       // 128*AST u16 per array
#define BUF_E  (4 * TILE_E)
#define GEMM_DSMEM (2 * BUF_E * 2)   // 81920 bytes

__global__ void __launch_bounds__(256, 2) k_gemm_mma(
    int layer, const float* __restrict__ bl)
{
    extern __shared__ uint16_t dsm[];
    __shared__ float bias_s[128];

    const uint16_t* rsh;
    const uint16_t* rsl;
    float*    hout;
    uint16_t* outh;
    uint16_t* outl;
    uint16_t* outf;
    int woff, relu, emit;
    if (layer == 0) {
        rsh = g_xh;  rsl = g_xl;  woff = 0;
        hout = g_hA; outh = g_hh0; outl = g_hl0; outf = g_hf0; relu = 1; emit = 1;
    } else if (layer == 1) {
        rsh = g_hh0; rsl = g_hl0; woff = 32768;
        hout = g_hB; outh = g_hh1; outl = g_hl1; outf = g_hf1; relu = 1; emit = 1;
    } else {
        rsh = g_hh1; rsl = g_hl1; woff = 65536;
        hout = g_hA; outh = nullptr; outl = nullptr; outf = nullptr; relu = 0; emit = 0;
    }

    int tid  = threadIdx.x;
    int wid  = tid >> 5;
    int lane = tid & 31;
    int nb   = blockIdx.x * 128;
    int m0   = (wid & 3) * 32;
    int n0   = (wid >> 2) * 64;

    if (tid < 128) bias_s[tid] = bl[tid];

    int c0  = tid,       row0 = c0 >> 2, seg0 = c0 & 3;
    int c1  = tid + 256, row1 = c1 >> 2, seg1 = c1 & 3;

    auto copy_chunk = [&](int chunk, int buf) {
        int kk0 = (chunk & 3) * 32;
        const uint16_t* pAh = (chunk < 4) ? g_aggh : rsh;
        const uint16_t* pAl = (chunk < 4) ? g_aggl : rsl;
        const uint16_t* pBh = g_Wbh + woff + ((chunk < 4) ? 0 : 16384);
        const uint16_t* pBl = g_Wbl + woff + ((chunk < 4) ? 0 : 16384);
        uint16_t* bAh = dsm + buf * BUF_E;
        uint16_t* bAl = bAh + TILE_E;
        uint16_t* bBh = bAh + 2 * TILE_E;
        uint16_t* bBl = bAh + 3 * TILE_E;
#pragma unroll
        for (int r = 0; r < 2; r++) {
            int row = r ? row1 : row0;
            int seg = r ? seg1 : seg0;
            int node = nb + row;
            int go = row * 128 + kk0 + seg * 8;
            int so = row * AST + seg * 8;
            if (node < NN) {
                CP_A16(smem_u32(&bAh[so]), &pAh[node * 128 + kk0 + seg * 8]);
                CP_A16(smem_u32(&bAl[so]), &pAl[node * 128 + kk0 + seg * 8]);
            } else {
                *(uint4*)&bAh[so] = make_uint4(0, 0, 0, 0);
                *(uint4*)&bAl[so] = make_uint4(0, 0, 0, 0);
            }
            CP_A16(smem_u32(&bBh[so]), &pBh[go]);
            CP_A16(smem_u32(&bBl[so]), &pBl[go]);
        }
        CP_COMMIT;
    };

    float acc[2][8][4];
#pragma unroll
    for (int i = 0; i < 2; i++)
#pragma unroll
        for (int j = 0; j < 8; j++)
#pragma unroll
            for (int q = 0; q < 4; q++) acc[i][j][q] = 0.f;

    copy_chunk(0, 0);

    for (int chunk = 0; chunk < 8; chunk++) {
        int buf = chunk & 1;
        CP_WAIT0;
        __syncthreads();
        if (chunk < 7) copy_chunk(chunk + 1, buf ^ 1);

        uint16_t* bAh = dsm + buf * BUF_E;
        uint16_t* bAl = bAh + TILE_E;
        uint16_t* bBh = bAh + 2 * TILE_E;
        uint16_t* bBl = bAh + 3 * TILE_E;

#pragma unroll
        for (int ks = 0; ks < 32; ks += 16) {
            uint32_t ah[2][4], alr[2][4], bh[4][4], blr[4][4];
#pragma unroll
            for (int mt = 0; mt < 2; mt++) {
                int row = m0 + mt * 16 + (lane & 15);
                int col = ks + (lane >> 4) * 8;
                LDSM_X4(ah[mt],  smem_u32(&bAh[row * AST + col]));
                LDSM_X4(alr[mt], smem_u32(&bAl[row * AST + col]));
            }
#pragma unroll
            for (int bt = 0; bt < 4; bt++) {
                int row = n0 + bt * 16 + (lane & 7) + ((lane >> 4) & 1) * 8;
                int col = ks + ((lane >> 3) & 1) * 8;
                LDSM_X4(bh[bt],  smem_u32(&bBh[row * AST + col]));
                LDSM_X4(blr[bt], smem_u32(&bBl[row * AST + col]));
            }
#pragma unroll
            for (int mt = 0; mt < 2; mt++)
#pragma unroll
                for (int nt = 0; nt < 8; nt++) {
                    int bg = nt >> 1, pr = (nt & 1) * 2;
                    MMA_BF16(acc[mt][nt], ah[mt],  bh[bg][pr],  bh[bg][pr + 1]);
                    MMA_BF16(acc[mt][nt], alr[mt], bh[bg][pr],  bh[bg][pr + 1]);
                    MMA_BF16(acc[mt][nt], ah[mt],  blr[bg][pr], blr[bg][pr + 1]);
                }
        }
        __syncthreads();
    }

    // ---- epilogue ----
    int g  = lane >> 2;
    int tg = lane & 3;
#pragma unroll
    for (int mt = 0; mt < 2; mt++)
#pragma unroll
        for (int nt = 0; nt < 8; nt++) {
            int colb = n0 + nt * 8 + tg * 2;
            float b0 = bias_s[colb], b1 = bias_s[colb + 1];
#pragma unroll
            for (int half = 0; half < 2; half++) {
                int row = nb + m0 + mt * 16 + g + half * 8;
                if (row >= NN) continue;
                float v0 = acc[mt][nt][half * 2 + 0] + b0;
                float v1 = acc[mt][nt][half * 2 + 1] + b1;
                if (relu) { v0 = fmaxf(v0, 0.f); v1 = fmaxf(v1, 0.f); }
                *(float2*)&hout[row * 128 + colb] = make_float2(v0, v1);
                if (emit) {
                    uint16_t h0, l0, h1, l1;
                    bf16_split(v0, h0, l0);
                    bf16_split(v1, h1, l1);
                    *(uint32_t*)&outh[row * 128 + colb] =
                        (uint32_t)h0 | ((uint32_t)h1 << 16);
                    *(uint32_t*)&outl[row * 128 + colb] =
                        (uint32_t)l0 | ((uint32_t)l1 << 16);
                    __half2 f2 = __floats2half2_rn(v0, v1);
                    *(uint32_t*)&outf[row * 128 + colb] = *(uint32_t*)&f2;
                }
            }
        }
}

// ---------------- parallel global mean pool ---------------------------------
__global__ void k_pool_acc(const int* __restrict__ batch, float* __restrict__ out) {
    int c  = threadIdx.x;          // column
    int r0 = blockIdx.x * 256;
    int r1 = min(r0 + 256, NN);
    int curg = -1;
    float s = 0.f;
    for (int r = r0; r < r1; r++) {
        int g = batch[r];
        if (g != curg) {
            if (curg >= 0) atomicAdd(&out[curg * 128 + c], s);
            curg = g; s = 0.f;
        }
        s += g_hA[r * 128 + c];
    }
    if (curg >= 0) atomicAdd(&out[curg * 128 + c], s);
}

__global__ void k_pool_div(float* __restrict__ out) {
    int i = blockIdx.x * blockDim.x + threadIdx.x;
    if (i >= NG * DIM) return;
    int g = i >> 7;
    int cnt = g_gcnt[g];
    out[i] = out[i] / (float)max(cnt, 1);
}

// ---------------- launch ----------------------------------------------------
extern "C" void kernel_launch(void* const* d_in, const int* in_sizes, int n_in,
                              void* d_out, int out_size)
{
    const float* x     = (const float*)d_in[0];
    const int*   ei    = (const int*)d_in[1];
    const int*   batch = (const int*)d_in[2];
    const float* Wl0 = (const float*)d_in[3];
    const float* bl0 = (const float*)d_in[4];
    const float* Wr0 = (const float*)d_in[5];
    const float* Wl1 = (const float*)d_in[6];
    const float* bl1 = (const float*)d_in[7];
    const float* Wr1 = (const float*)d_in[8];
    const float* Wl2 = (const float*)d_in[9];
    const float* bl2 = (const float*)d_in[10];
    const float* Wr2 = (const float*)d_in[11];
    float* out = (float*)d_out;

    (void)cudaFuncSetAttribute(k_gemm_mma,
                               cudaFuncAttributeMaxDynamicSharedMemorySize,
                               GEMM_DSMEM);

    k_zero<<<(NN + 255) / 256, 256>>>(out);                                     // 1
    k_prep<<<(NN * DIM + 255) / 256, 256>>>(x, ei, batch,                       // 2
                                            Wl0, Wr0, Wl1, Wr1, Wl2, Wr2);

    int agg_blocks  = (NN * 32 + 255) / 256;
    int gemm_blocks = (NN + 127) / 128;   // 391

    k_agg<<<agg_blocks, 256>>>(0);                                              // 3
    k_gemm_mma<<<gemm_blocks, 256, GEMM_DSMEM>>>(0, bl0);                       // 4 <- ncu lands here
    k_agg<<<agg_blocks, 256>>>(1);                                              // 5
    k_gemm_mma<<<gemm_blocks, 256, GEMM_DSMEM>>>(1, bl1);                       // 6
    k_agg<<<agg_blocks, 256>>>(2);                                              // 7
    k_gemm_mma<<<gemm_blocks, 256, GEMM_DSMEM>>>(2, bl2);                       // 8
    k_pool_acc<<<(NN + 255) / 256, 128>>>(batch, out);                          // 9
    k_pool_div<<<(NG * DIM + 255) / 256, 256>>>(out);                           // 10
}

// round 15
// speedup vs baseline: 1.4664x; 1.4664x over previous
#include <cuda_runtime.h>
#include <cuda_fp16.h>
#include <cstdint>

#define NN 50000
#define NE 800000
#define DIM 128
#define NG 64
#define SEG 64            // fixed CSR slots per node (max deg ~45 for Poisson(16))

// ---------------- static device scratch -------------------------------------
static __device__ float    g_hA [NN * DIM];       // fp32 final-layer output (pool input)
static __device__ uint16_t g_aggf[NN * DIM];      // fp16 mean-agg
static __device__ uint16_t g_xf16[NN * DIM];      // fp16 x      (layer0 gather+rs)
static __device__ uint16_t g_hf0 [NN * DIM];      // fp16 h0     (layer1 gather+rs)
static __device__ uint16_t g_hf1 [NN * DIM];      // fp16 h1     (layer2 gather+rs)
static __device__ uint16_t g_Wf16[6 * 16384];     // fp16 Wl0,Wr0,Wl1,Wr1,Wl2,Wr2
static __device__ int   g_deg[NN];                // doubles as fill cursor
static __device__ int   g_csr[NN * SEG];
static __device__ int   g_gcnt[NG];

// ---------------- helpers ----------------------------------------------------
__device__ __forceinline__ uint32_t smem_u32(const void* p) {
    uint32_t a;
    asm("{ .reg .u64 t; cvta.to.shared.u64 t, %1; cvt.u32.u64 %0, t; }"
        : "=r"(a) : "l"(p));
    return a;
}

#define LDSM_X4(r, addr) \
    asm volatile("ldmatrix.sync.aligned.m8n8.x4.shared.b16 {%0,%1,%2,%3}, [%4];" \
        : "=r"((r)[0]), "=r"((r)[1]), "=r"((r)[2]), "=r"((r)[3]) : "r"(addr))

#define MMA_F16(d, a, b0v, b1v) \
    asm volatile("mma.sync.aligned.m16n8k16.row.col.f32.f16.f16.f32 " \
        "{%0,%1,%2,%3}, {%4,%5,%6,%7}, {%8,%9}, {%0,%1,%2,%3};" \
        : "+f"((d)[0]), "+f"((d)[1]), "+f"((d)[2]), "+f"((d)[3]) \
        : "r"((a)[0]), "r"((a)[1]), "r"((a)[2]), "r"((a)[3]), \
          "r"(b0v), "r"(b1v))

#define CP_A16(dst32, src) \
    asm volatile("cp.async.cg.shared.global [%0], [%1], 16;" \
        :: "r"(dst32), "l"(src) : "memory")
#define CP_COMMIT  asm volatile("cp.async.commit_group;" ::: "memory")
#define CP_WAIT0   asm volatile("cp.async.wait_group 0;" ::: "memory")

// ---------------- init --------------------------------------------------------
__global__ void k_zero(float* __restrict__ out) {
    int i = blockIdx.x * blockDim.x + threadIdx.x;
    if (i < NN) g_deg[i] = 0;
    if (i < NG) g_gcnt[i] = 0;
    if (i < NG * DIM) out[i] = 0.0f;      // pool accumulators (d_out poisoned)
}

// cvtX (fp16) + CSR build + graph count + all W conversions (fp16)
__global__ void k_prep(const float* __restrict__ x, const int* __restrict__ ei,
                       const int* __restrict__ batch,
                       const float* __restrict__ w0, const float* __restrict__ w1,
                       const float* __restrict__ w2, const float* __restrict__ w3,
                       const float* __restrict__ w4, const float* __restrict__ w5)
{
    int i = blockIdx.x * blockDim.x + threadIdx.x;
    if (i < NN * DIM)
        g_xf16[i] = __half_as_ushort(__float2half_rn(x[i]));
    if (i < NE) {
        int s = ei[i];
        int d = ei[NE + i];
        int pos = atomicAdd(&g_deg[d], 1);
        g_csr[d * SEG + pos] = s;
    }
    if (i < NN) atomicAdd(&g_gcnt[batch[i]], 1);
    if (i < 6 * 16384) {
        int sel = i >> 14;
        int off = i & 16383;
        const float* w = (sel == 0) ? w0 : (sel == 1) ? w1 : (sel == 2) ? w2
                       : (sel == 3) ? w3 : (sel == 4) ? w4 : w5;
        g_Wf16[i] = __half_as_ushort(__float2half_rn(w[off]));
    }
}

// ---------------- mean aggregation (warp per node, fp16 gather) -------------
// R13-measured form: uint2/lane (4 fp16), 8-deep unroll, fp32 accumulate.
__global__ void k_agg(int sel) {
    const uint16_t* hf = (sel == 0) ? g_xf16 : ((sel == 1) ? g_hf0 : g_hf1);
    int gw   = (blockIdx.x * blockDim.x + threadIdx.x) >> 5;
    int lane = threadIdx.x & 31;
    if (gw >= NN) return;
    int start = gw * SEG;
    int d     = g_deg[gw];
    const uint2* x2 = (const uint2*)hf;
    float a0 = 0.f, a1 = 0.f, a2 = 0.f, a3 = 0.f;
    int j = 0;
    for (; j + 8 <= d; j += 8) {
        int4 sa = *(const int4*)&g_csr[start + j];
        int4 sb = *(const int4*)&g_csr[start + j + 4];
        uint2 u0 = x2[sa.x * 32 + lane];
        uint2 u1 = x2[sa.y * 32 + lane];
        uint2 u2 = x2[sa.z * 32 + lane];
        uint2 u3 = x2[sa.w * 32 + lane];
        uint2 u4 = x2[sb.x * 32 + lane];
        uint2 u5 = x2[sb.y * 32 + lane];
        uint2 u6 = x2[sb.z * 32 + lane];
        uint2 u7 = x2[sb.w * 32 + lane];
#define ACC(u) { float2 pa = __half22float2(*(__half2*)&(u).x); \
                 float2 pb = __half22float2(*(__half2*)&(u).y); \
                 a0 += pa.x; a1 += pa.y; a2 += pb.x; a3 += pb.y; }
        ACC(u0) ACC(u1) ACC(u2) ACC(u3) ACC(u4) ACC(u5) ACC(u6) ACC(u7)
    }
    for (; j + 4 <= d; j += 4) {
        int4 si = *(const int4*)&g_csr[start + j];
        uint2 u0 = x2[si.x * 32 + lane];
        uint2 u1 = x2[si.y * 32 + lane];
        uint2 u2 = x2[si.z * 32 + lane];
        uint2 u3 = x2[si.w * 32 + lane];
        ACC(u0) ACC(u1) ACC(u2) ACC(u3)
    }
    for (; j < d; j++) {
        int s0 = g_csr[start + j];
        uint2 u = x2[s0 * 32 + lane];
        ACC(u)
    }
#undef ACC
    float inv = (d > 0) ? 1.0f / (float)d : 0.0f;
    __half2 p0 = __floats2half2_rn(a0 * inv, a1 * inv);
    __half2 p1 = __floats2half2_rn(a2 * inv, a3 * inv);
    int idx = gw * 128 + lane * 4;
    *(uint2*)&g_aggf[idx] = make_uint2(*(uint32_t*)&p0, *(uint32_t*)&p1);
}

// ---------------- fp16 tensor GEMM (cp.async double-buffered) ---------------
#define AST 40            // smem row stride in u16 (80B -> conflict-free ldmatrix)
#define TILE_E 5120       // 128*AST u16 per array
#define BUF_E  (2 * TILE_E)          // A + B per buffer
#define GEMM_DSMEM (2 * BUF_E * 2)   // 40960 bytes

__global__ void __launch_bounds__(256, 2) k_gemm_mma(
    int layer, const float* __restrict__ bl)
{
    extern __shared__ uint16_t dsm[];
    __shared__ float bias_s[128];

    const uint16_t* rs;      // self features (fp16)
    uint16_t* outf;          // fp16 output table (layers 0,1)
    int woff, relu;
    if (layer == 0)      { rs = g_xf16; woff = 0;     outf = g_hf0; relu = 1; }
    else if (layer == 1) { rs = g_hf0;  woff = 32768; outf = g_hf1; relu = 1; }
    else                 { rs = g_hf1;  woff = 65536; outf = nullptr; relu = 0; }

    int tid  = threadIdx.x;
    int wid  = tid >> 5;
    int lane = tid & 31;
    int nb   = blockIdx.x * 128;
    int m0   = (wid & 3) * 32;
    int n0   = (wid >> 2) * 64;

    if (tid < 128) bias_s[tid] = bl[tid];

    int c0  = tid,       row0 = c0 >> 2, seg0 = c0 & 3;
    int c1  = tid + 256, row1 = c1 >> 2, seg1 = c1 & 3;

    auto copy_chunk = [&](int chunk, int buf) {
        int kk0 = (chunk & 3) * 32;
        const uint16_t* pA = (chunk < 4) ? g_aggf : rs;
        const uint16_t* pB = g_Wf16 + woff + ((chunk < 4) ? 0 : 16384);
        uint16_t* bA = dsm + buf * BUF_E;
        uint16_t* bB = bA + TILE_E;
#pragma unroll
        for (int r = 0; r < 2; r++) {
            int row = r ? row1 : row0;
            int seg = r ? seg1 : seg0;
            int node = nb + row;
            int go = row * 128 + kk0 + seg * 8;
            int so = row * AST + seg * 8;
            if (node < NN)
                CP_A16(smem_u32(&bA[so]), &pA[node * 128 + kk0 + seg * 8]);
            else
                *(uint4*)&bA[so] = make_uint4(0, 0, 0, 0);
            CP_A16(smem_u32(&bB[so]), &pB[go]);
        }
        CP_COMMIT;
    };

    float acc[2][8][4];
#pragma unroll
    for (int i = 0; i < 2; i++)
#pragma unroll
        for (int j = 0; j < 8; j++)
#pragma unroll
            for (int q = 0; q < 4; q++) acc[i][j][q] = 0.f;

    copy_chunk(0, 0);

    for (int chunk = 0; chunk < 8; chunk++) {
        int buf = chunk & 1;
        CP_WAIT0;
        __syncthreads();
        if (chunk < 7) copy_chunk(chunk + 1, buf ^ 1);

        uint16_t* bA = dsm + buf * BUF_E;
        uint16_t* bB = bA + TILE_E;

#pragma unroll
        for (int ks = 0; ks < 32; ks += 16) {
            uint32_t af[2][4], bf[4][4];
#pragma unroll
            for (int mt = 0; mt < 2; mt++) {
                int row = m0 + mt * 16 + (lane & 15);
                int col = ks + (lane >> 4) * 8;
                LDSM_X4(af[mt], smem_u32(&bA[row * AST + col]));
            }
#pragma unroll
            for (int bt = 0; bt < 4; bt++) {
                int row = n0 + bt * 16 + (lane & 7) + ((lane >> 4) & 1) * 8;
                int col = ks + ((lane >> 3) & 1) * 8;
                LDSM_X4(bf[bt], smem_u32(&bB[row * AST + col]));
            }
#pragma unroll
            for (int mt = 0; mt < 2; mt++)
#pragma unroll
                for (int nt = 0; nt < 8; nt++) {
                    int bg = nt >> 1, pr = (nt & 1) * 2;
                    MMA_F16(acc[mt][nt], af[mt], bf[bg][pr], bf[bg][pr + 1]);
                }
        }
        __syncthreads();
    }

    // ---- epilogue ----
    int g  = lane >> 2;
    int tg = lane & 3;
#pragma unroll
    for (int mt = 0; mt < 2; mt++)
#pragma unroll
        for (int nt = 0; nt < 8; nt++) {
            int colb = n0 + nt * 8 + tg * 2;
            float b0 = bias_s[colb], b1 = bias_s[colb + 1];
#pragma unroll
            for (int half = 0; half < 2; half++) {
                int row = nb + m0 + mt * 16 + g + half * 8;
                if (row >= NN) continue;
                float v0 = acc[mt][nt][half * 2 + 0] + b0;
                float v1 = acc[mt][nt][half * 2 + 1] + b1;
                if (relu) { v0 = fmaxf(v0, 0.f); v1 = fmaxf(v1, 0.f); }
                if (layer == 2) {
                    *(float2*)&g_hA[row * 128 + colb] = make_float2(v0, v1);
                } else {
                    __half2 f2 = __floats2half2_rn(v0, v1);
                    *(uint32_t*)&outf[row * 128 + colb] = *(uint32_t*)&f2;
                }
            }
        }
}

// ---------------- parallel global mean pool ---------------------------------
__global__ void k_pool_acc(const int* __restrict__ batch, float* __restrict__ out) {
    int c  = threadIdx.x;          // column
    int r0 = blockIdx.x * 256;
    int r1 = min(r0 + 256, NN);
    int curg = -1;
    float s = 0.f;
    for (int r = r0; r < r1; r++) {
        int g = batch[r];
        if (g != curg) {
            if (curg >= 0) atomicAdd(&out[curg * 128 + c], s);
            curg = g; s = 0.f;
        }
        s += g_hA[r * 128 + c];
    }
    if (curg >= 0) atomicAdd(&out[curg * 128 + c], s);
}

__global__ void k_pool_div(float* __restrict__ out) {
    int i = blockIdx.x * blockDim.x + threadIdx.x;
    if (i >= NG * DIM) return;
    int g = i >> 7;
    int cnt = g_gcnt[g];
    out[i] = out[i] / (float)max(cnt, 1);
}

// ---------------- launch ----------------------------------------------------
extern "C" void kernel_launch(void* const* d_in, const int* in_sizes, int n_in,
                              void* d_out, int out_size)
{
    const float* x     = (const float*)d_in[0];
    const int*   ei    = (const int*)d_in[1];
    const int*   batch = (const int*)d_in[2];
    const float* Wl0 = (const float*)d_in[3];
    const float* bl0 = (const float*)d_in[4];
    const float* Wr0 = (const float*)d_in[5];
    const float* Wl1 = (const float*)d_in[6];
    const float* bl1 = (const float*)d_in[7];
    const float* Wr1 = (const float*)d_in[8];
    const float* Wl2 = (const float*)d_in[9];
    const float* bl2 = (const float*)d_in[10];
    const float* Wr2 = (const float*)d_in[11];
    float* out = (float*)d_out;

    (void)cudaFuncSetAttribute(k_gemm_mma,
                               cudaFuncAttributeMaxDynamicSharedMemorySize,
                               GEMM_DSMEM);

    k_zero<<<(NN + 255) / 256, 256>>>(out);                                     // 1
    k_prep<<<(NN * DIM + 255) / 256, 256>>>(x, ei, batch,                       // 2
                                            Wl0, Wr0, Wl1, Wr1, Wl2, Wr2);

    int agg_blocks  = (NN * 32 + 255) / 256;
    int gemm_blocks = (NN + 127) / 128;   // 391

    k_agg<<<agg_blocks, 256>>>(0);                                              // 3
    k_gemm_mma<<<gemm_blocks, 256, GEMM_DSMEM>>>(0, bl0);                       // 4 <- ncu lands here
    k_agg<<<agg_blocks, 256>>>(1);                                              // 5
    k_gemm_mma<<<gemm_blocks, 256, GEMM_DSMEM>>>(1, bl1);                       // 6
    k_agg<<<agg_blocks, 256>>>(2);                                              // 7
    k_gemm_mma<<<gemm_blocks, 256, GEMM_DSMEM>>>(2, bl2);                       // 8
    k_pool_acc<<<(NN + 255) / 256, 128>>>(batch, out);                          // 9
    k_pool_div<<<(NG * DIM + 255) / 256, 256>>>(out);                           // 10
}